// round 7
// baseline (speedup 1.0000x reference)
#include <cuda_runtime.h>

// x shape [3, 5, 32, 64, 32, 32] -> 30720 images of 32x32
#define N_IMGS   30720
#define N_OUT    480
#define PATCHES  64
#define HW       1024
#define WPB      8          // warps (=images) per block
#define MAXRUNS  512        // <= 16 runs/row * 32 rows

__device__ int g_counts[N_IMGS];

// Union-find over runs. Entries: low 16 bits = parent id (<512),
// high 16 bits = component count (only written in the count phase).

// Path-halving find. ONLY safe during merge phase (high bits all zero,
// plain store to a non-root races only with monotone atomicMin links,
// which the umerge retry protocol tolerates).
__device__ __forceinline__ int ufind_halve(unsigned* L, int a) {
    int p = (int)L[a];
    while (p != a) {
        int gp = (int)L[p];
        if (gp != p) L[a] = (unsigned)gp;   // halve
        a = gp;
        p = (int)L[a];
    }
    return a;
}

// Read-only find for the count phase (high bits may hold counts; mask them,
// never write).
__device__ __forceinline__ int ufind_ro(const unsigned* L, int a) {
    int p = (int)(L[a] & 0xffffu);
    while (p != a) { a = p; p = (int)(L[a] & 0xffffu); }
    return a;
}

__device__ __forceinline__ void umerge(unsigned* L, int a, int b) {
    while (true) {
        a = ufind_halve(L, a);
        b = ufind_halve(L, b);
        if (a == b) return;
        int mn = min(a, b), mx = max(a, b);
        unsigned old = atomicMin(&L[mx], (unsigned)mn);
        if (old == (unsigned)mx) return;    // linked root mx -> mn
        a = mn; b = (int)old;               // lost race; keep merging
    }
}

// Isolate the lowest run of `rem` (maximal block of consecutive 1s).
// Carry from +low clears exactly that run; XOR exposes it. Wraps safely at bit 31.
__device__ __forceinline__ unsigned lowest_run(unsigned rem, unsigned low) {
    return rem & (rem ^ (rem + low));
}

// One warp per 32x32 image; lane = row.
__global__ void __launch_bounds__(32 * WPB)
ccl_kernel(const float* __restrict__ x) {
    __shared__ unsigned UF[WPB][MAXRUNS];

    const int lane = threadIdx.x & 31;
    const int warp = threadIdx.x >> 5;
    const int img  = blockIdx.x * WPB + warp;
    const float* p = x + (size_t)img * HW;

    // Row bitmasks via 32 coalesced loads + ballots (streaming: read-once data).
    unsigned m = 0;
    #pragma unroll
    for (int r = 0; r < 32; r++) {
        unsigned b = __ballot_sync(0xFFFFFFFFu, __ldcs(p + r * 32 + lane) != 0.0f);
        if (lane == r) m = b;
    }

    // Run starts; per-row run-id base via warp scan.
    const unsigned start = m & ~(m << 1);
    const int nmine = __popc(start);
    int scan = nmine;
    #pragma unroll
    for (int o = 1; o < 32; o <<= 1) {
        int v = __shfl_up_sync(0xFFFFFFFFu, scan, o);
        if (lane >= o) scan += v;
    }
    const int base  = scan - nmine;
    const int total = __shfl_sync(0xFFFFFFFFu, scan, 31);

    unsigned* uf = UF[warp];
    for (int i = lane; i < total; i += 32) uf[i] = (unsigned)i;
    __syncwarp();

    // Next-row info (lane 31 has none).
    unsigned nm     = __shfl_down_sync(0xFFFFFFFFu, m, 1);
    unsigned nstart = __shfl_down_sync(0xFFFFFFFFu, start, 1);
    int      nbase  = __shfl_down_sync(0xFFFFFFFFu, base, 1);
    if (lane == 31) nm = 0;

    // Merge runs overlapping between row and row+1.
    {
        unsigned rem = m;
        int idx = base;
        while (rem) {
            unsigned low   = rem & (unsigned)(-(int)rem);
            unsigned rmask = lowest_run(rem, low);
            rem &= ~rmask;
            unsigned ov   = rmask & nm;
            unsigned segs = ov & ~(ov << 1);
            while (segs) {
                int j = __ffs(segs) - 1;
                segs &= segs - 1;
                unsigned below = (2u << j) - 1;          // bits 0..j (j=31 wraps to all)
                int b = __popc(nstart & below) - 1;      // next-row run containing bit j
                umerge(uf, idx, nbase + b);
            }
            idx++;
        }
    }
    __syncwarp();

    // Flatten: 3 pointer-jumping passes (optimization; count uses full find anyway).
    #pragma unroll
    for (int pass = 0; pass < 3; pass++) {
        for (int i = lane; i < total; i += 32) {
            unsigned q = uf[i];
            uf[i] = uf[q];
        }
        __syncwarp();
    }

    // Count phase: accumulate component sizes into the roots' HIGH 16 bits,
    // warp-aggregated per distinct root to avoid conflicted shared atomics.
    {
        unsigned rem = m;
        int idx = base;
        while (__any_sync(0xFFFFFFFFu, rem != 0)) {
            const bool act = (rem != 0);
            int root = -1, sz = 0;
            if (act) {
                unsigned low   = rem & (unsigned)(-(int)rem);
                unsigned rmask = lowest_run(rem, low);
                rem &= ~rmask;
                sz   = __popc(rmask);
                root = ufind_ro(uf, idx);
                idx++;
            }
            unsigned amask = __ballot_sync(0xFFFFFFFFu, act);
            if (act) {
                unsigned grp = __match_any_sync(amask, root);
                int tot = __reduce_add_sync(grp, sz);
                if (lane == __ffs(grp) - 1)
                    atomicAdd(&uf[root], ((unsigned)tot) << 16);
            }
        }
    }
    __syncwarp();

    // Max component size; background (label 0 in reference) competes too.
    int v = 0;
    for (int i = lane; i < total; i += 32) v = max(v, (int)(uf[i] >> 16));
    int bg = 32 - __popc(m);
    #pragma unroll
    for (int o = 16; o > 0; o >>= 1) {
        v  = max(v, __shfl_xor_sync(0xFFFFFFFFu, v, o));
        bg += __shfl_xor_sync(0xFFFFFFFFu, bg, o);
    }
    if (lane == 0) g_counts[img] = max(v, bg);
}

// One warp per output: sum 64 patch counts, truncating divide, write float.
__global__ void reduce_kernel(float* __restrict__ out) {
    const int o = blockIdx.x;
    const int lane = threadIdx.x;
    const int* c = &g_counts[o * PATCHES];
    int s = c[lane] + c[lane + 32];
    #pragma unroll
    for (int sh = 16; sh > 0; sh >>= 1)
        s += __shfl_xor_sync(0xFFFFFFFFu, s, sh);
    if (lane == 0) out[o] = (float)(s / PATCHES);
}

// No-op launches to steer ncu (-s 5 -c 1) onto ccl_kernel: with 5 launches
// per replay, the 6th launch overall is ccl_kernel of the second replay.
__global__ void noop_kernel() {}

extern "C" void kernel_launch(void* const* d_in, const int* in_sizes, int n_in,
                              void* d_out, int out_size) {
    const float* x = (const float*)d_in[0];
    float* out = (float*)d_out;

    ccl_kernel<<<N_IMGS / WPB, 32 * WPB>>>(x);
    reduce_kernel<<<N_OUT, 32>>>(out);
    noop_kernel<<<1, 32>>>();
    noop_kernel<<<1, 32>>>();
    noop_kernel<<<1, 32>>>();
}

// round 8
// speedup vs baseline: 1.0639x; 1.0639x over previous
#include <cuda_runtime.h>

// x shape [3, 5, 32, 64, 32, 32] -> 30720 images of 32x32
#define N_IMGS   30720
#define N_OUT    480
#define PATCHES  64
#define HW       1024
#define WPB      8          // warps (=images) per block
#define MAXRUNS  512        // <= 16 runs/row * 32 rows

// Cross-block accumulation scratch. Zero-initialized at module load and
// self-reset by the finisher warp each replay -> graph-replay safe.
__device__ int g_sum[N_OUT];
__device__ int g_cnt[N_OUT];

// ---- union-find over runs in per-warp shared memory ----
// Entries: low 16 bits = parent id (<512), high 16 bits = component count
// (written only in the count phase).

__device__ __forceinline__ int ufind_halve(unsigned* L, int a) {
    int p = (int)L[a];
    while (p != a) {
        int gp = (int)L[p];
        if (gp != p) L[a] = (unsigned)gp;   // path halving
        a = gp;
        p = (int)L[a];
    }
    return a;
}

__device__ __forceinline__ int ufind_ro(const unsigned* L, int a) {
    int p = (int)(L[a] & 0xffffu);
    while (p != a) { a = p; p = (int)(L[a] & 0xffffu); }
    return a;
}

__device__ __forceinline__ void umerge(unsigned* L, int a, int b) {
    while (true) {
        a = ufind_halve(L, a);
        b = ufind_halve(L, b);
        if (a == b) return;
        int mn = min(a, b), mx = max(a, b);
        unsigned old = atomicMin(&L[mx], (unsigned)mn);
        if (old == (unsigned)mx) return;
        a = mn; b = (int)old;
    }
}

// Isolate the lowest maximal run of 1s in rem (low = lowest set bit of rem).
__device__ __forceinline__ unsigned lowest_run(unsigned rem, unsigned low) {
    return rem & (rem ^ (rem + low));   // carry clears the run; XOR exposes it
}

// One warp per 32x32 image; lane = row. Single fused kernel.
__global__ void __launch_bounds__(32 * WPB)
ccl_kernel(const float* __restrict__ x, float* __restrict__ out) {
    __shared__ unsigned UF[WPB][MAXRUNS];

    const int lane = threadIdx.x & 31;
    const int warp = threadIdx.x >> 5;
    const int img  = blockIdx.x * WPB + warp;
    const float* p = x + (size_t)img * HW;

    // Row bitmasks: 32 coalesced streaming loads + ballots.
    unsigned m = 0;
    #pragma unroll
    for (int r = 0; r < 32; r++) {
        unsigned b = __ballot_sync(0xFFFFFFFFu, __ldcs(p + r * 32 + lane) != 0.0f);
        if (lane == r) m = b;
    }

    // Run starts; per-row run-id base via warp scan.
    const unsigned start = m & ~(m << 1);
    const int nmine = __popc(start);
    int scan = nmine;
    #pragma unroll
    for (int o = 1; o < 32; o <<= 1) {
        int v = __shfl_up_sync(0xFFFFFFFFu, scan, o);
        if (lane >= o) scan += v;
    }
    const int base  = scan - nmine;
    const int total = __shfl_sync(0xFFFFFFFFu, scan, 31);

    unsigned* uf = UF[warp];
    for (int i = lane; i < total; i += 32) uf[i] = (unsigned)i;
    __syncwarp();

    // Next-row info (lane 31 has none).
    unsigned nm     = __shfl_down_sync(0xFFFFFFFFu, m, 1);
    unsigned nstart = __shfl_down_sync(0xFFFFFFFFu, start, 1);
    int      nbase  = __shfl_down_sync(0xFFFFFFFFu, base, 1);
    if (lane == 31) nm = 0;

    // FLAT merge loop: each maximal segment of (m & nm) is one inter-row edge
    // between the run of m and the run of nm containing its start bit.
    {
        unsigned ov   = m & nm;
        unsigned segs = ov & ~(ov << 1);
        while (segs) {
            int j = __ffs(segs) - 1;
            segs &= segs - 1;
            unsigned below = (2u << j) - 1;            // bits 0..j (j=31 wraps to all)
            int a = base  + __popc(start  & below) - 1;
            int b = nbase + __popc(nstart & below) - 1;
            umerge(uf, a, b);
        }
    }
    __syncwarp();

    // Flatten: 2 pointer-jumping passes.
    #pragma unroll
    for (int pass = 0; pass < 2; pass++) {
        for (int i = lane; i < total; i += 32) {
            unsigned q = uf[i];
            uf[i] = uf[q];
        }
        __syncwarp();
    }

    // Count phase: per-run sizes into roots' HIGH 16 bits, warp-aggregated
    // per distinct root to avoid conflicted shared atomics.
    {
        unsigned rem = m;
        int idx = base;
        while (__any_sync(0xFFFFFFFFu, rem != 0)) {
            const bool act = (rem != 0);
            int root = -1, sz = 0;
            if (act) {
                unsigned low   = rem & (unsigned)(-(int)rem);
                unsigned rmask = lowest_run(rem, low);
                rem &= ~rmask;
                sz   = __popc(rmask);
                root = ufind_ro(uf, idx);
                idx++;
            }
            unsigned amask = __ballot_sync(0xFFFFFFFFu, act);
            if (act) {
                unsigned grp = __match_any_sync(amask, root);
                int tot = __reduce_add_sync(grp, sz);
                if (lane == __ffs(grp) - 1)
                    atomicAdd(&uf[root], ((unsigned)tot) << 16);
            }
        }
    }
    __syncwarp();

    // Max component size; background count (label 0 in reference) competes.
    int v = 0;
    for (int i = lane; i < total; i += 32) v = max(v, (int)(uf[i] >> 16));
    int bg = 32 - __popc(m);
    #pragma unroll
    for (int o = 16; o > 0; o >>= 1) {
        v  = max(v, __shfl_xor_sync(0xFFFFFFFFu, v, o));
        bg += __shfl_xor_sync(0xFFFFFFFFu, bg, o);
    }

    // Fused reduction: last warp of each 64-patch group finishes the output.
    if (lane == 0) {
        const int my = max(v, bg);
        const int o = img >> 6;                 // img / PATCHES
        atomicAdd(&g_sum[o], my);
        __threadfence();                        // release my sum before cnt
        int n = atomicAdd(&g_cnt[o], 1);
        if (n == PATCHES - 1) {                 // I'm the 64th arriver
            __threadfence();                    // acquire all sums
            int total_s = atomicExch(&g_sum[o], 0);   // read + reset for next replay
            out[o] = (float)(total_s / PATCHES);      // truncating int divide
            atomicExch(&g_cnt[o], 0);                 // reset for next replay
        }
    }
}

extern "C" void kernel_launch(void* const* d_in, const int* in_sizes, int n_in,
                              void* d_out, int out_size) {
    const float* x = (const float*)d_in[0];
    float* out = (float*)d_out;
    ccl_kernel<<<N_IMGS / WPB, 32 * WPB>>>(x, out);
}

// round 9
// speedup vs baseline: 1.9017x; 1.7876x over previous
#include <cuda_runtime.h>

// x shape [3, 5, 32, 64, 32, 32] -> 30720 images of 32x32
#define N_IMGS   30720
#define N_OUT    480
#define PATCHES  64
#define HW       1024
#define WPB      8          // warps (=images) per block
#define MAXRUNS  512        // <= 16 runs/row * 32 rows

// Cross-block accumulation scratch; self-resetting each replay.
__device__ int g_sum[N_OUT];
__device__ int g_cnt[N_OUT];

// UF word: [31:16] parent id, [15:0] static run size (merge phase) /
// accumulated component count at roots (count phase). Sizes are static during
// the merge phase, so all racing atomicMin hookers write identical low bits.

// Find with path halving; returns root, and the word observed at the root.
__device__ __forceinline__ int ufind(unsigned* L, int a, unsigned& wroot) {
    while (true) {
        unsigned w = L[a];
        int p = (int)(w >> 16);
        if (p == a) { wroot = w; return a; }
        unsigned pw = L[p];
        int gp = (int)(pw >> 16);
        if (gp == p) { wroot = pw; return p; }
        L[a] = ((unsigned)gp << 16) | (w & 0xffffu);   // halve (low bits kept)
        a = gp;
    }
}

// Read-only find (count phase: low bits of roots are being red.add'ed).
__device__ __forceinline__ int ufind_ro(const unsigned* L, int a) {
    int p = (int)(L[a] >> 16);
    while (p != a) { a = p; p = (int)(L[a] >> 16); }
    return a;
}

__device__ __forceinline__ void umerge(unsigned* L, int a, int b) {
    while (true) {
        unsigned wa, wb;
        a = ufind(L, a, wa);
        b = ufind(L, b, wb);
        if (a == b) return;
        int mn, mx; unsigned wmx;
        if (a < b) { mn = a; mx = b; wmx = wb; }
        else       { mn = b; mx = a; wmx = wa; }
        unsigned old = atomicMin(&L[mx], ((unsigned)mn << 16) | (wmx & 0xffffu));
        if ((int)(old >> 16) == mx) return;    // linked root mx -> mn
        a = mn; b = (int)(old >> 16);          // lost race; merge survivors
    }
}

// Isolate lowest maximal run of 1s (low = lowest set bit of rem).
__device__ __forceinline__ unsigned lowest_run(unsigned rem, unsigned low) {
    return rem & (rem ^ (rem + low));
}

// Spread 8 bits so bit k lands at position 4k.
__device__ __forceinline__ unsigned spread4(unsigned x) {
    x = (x | (x << 12)) & 0x000F000Fu;
    x = (x | (x << 6))  & 0x03030303u;
    x = (x | (x << 3))  & 0x11111111u;
    return x;
}

// One warp per 32x32 image; lane = row.
__global__ void __launch_bounds__(32 * WPB)
ccl_kernel(const float* __restrict__ x, float* __restrict__ out) {
    __shared__ unsigned UF[WPB][MAXRUNS];

    const int lane = threadIdx.x & 31;
    const int warp = threadIdx.x >> 5;
    const int img  = blockIdx.x * WPB + warp;

    // ---- Build row bitmasks: 8 coalesced float4 loads + 4 ballots each ----
    // iter i, lane l: float4 #(i*32+l) covers row i*4 + l/8, cols 4*(l%8)+{0..3}.
    // Lane r's row lives in iteration i = r>>2, byte s = r&3 of each ballot.
    const float4* p4 = (const float4*)(x + (size_t)img * HW);
    unsigned c0 = 0, c1 = 0, c2 = 0, c3 = 0;
    #pragma unroll
    for (int i = 0; i < 8; i++) {
        float4 v = __ldcs(&p4[i * 32 + lane]);
        unsigned b0 = __ballot_sync(0xFFFFFFFFu, v.x != 0.0f);
        unsigned b1 = __ballot_sync(0xFFFFFFFFu, v.y != 0.0f);
        unsigned b2 = __ballot_sync(0xFFFFFFFFu, v.z != 0.0f);
        unsigned b3 = __ballot_sync(0xFFFFFFFFu, v.w != 0.0f);
        if ((lane >> 2) == i) {
            int sh = (lane & 3) * 8;
            c0 = (b0 >> sh) & 0xffu;
            c1 = (b1 >> sh) & 0xffu;
            c2 = (b2 >> sh) & 0xffu;
            c3 = (b3 >> sh) & 0xffu;
        }
    }
    const unsigned m = spread4(c0) | (spread4(c1) << 1)
                     | (spread4(c2) << 2) | (spread4(c3) << 3);

    // ---- Run starts; per-row run-id base via warp scan ----
    const unsigned start = m & ~(m << 1);
    const int nmine = __popc(start);
    int scan = nmine;
    #pragma unroll
    for (int o = 1; o < 32; o <<= 1) {
        int v = __shfl_up_sync(0xFFFFFFFFu, scan, o);
        if (lane >= o) scan += v;
    }
    const int base  = scan - nmine;
    const int total = __shfl_sync(0xFFFFFFFFu, scan, 31);

    // ---- Init: each lane writes its runs' (parent=self | size) words ----
    unsigned* uf = UF[warp];
    {
        unsigned rem = m;
        int idx = base;
        while (rem) {
            unsigned low   = rem & (unsigned)(-(int)rem);
            unsigned rmask = lowest_run(rem, low);
            rem &= ~rmask;
            uf[idx] = ((unsigned)idx << 16) | (unsigned)__popc(rmask);
            idx++;
        }
    }
    __syncwarp();

    // ---- Merge inter-row edges (flat loop over segments of m & next-row) ----
    unsigned nm     = __shfl_down_sync(0xFFFFFFFFu, m, 1);
    unsigned nstart = __shfl_down_sync(0xFFFFFFFFu, start, 1);
    int      nbase  = __shfl_down_sync(0xFFFFFFFFu, base, 1);
    if (lane == 31) nm = 0;
    {
        unsigned ov   = m & nm;
        unsigned segs = ov & ~(ov << 1);
        while (segs) {
            int j = __ffs(segs) - 1;
            segs &= segs - 1;
            unsigned below = (2u << j) - 1;            // bits 0..j (j=31 -> all)
            int a = base  + __popc(start  & below) - 1;
            int b = nbase + __popc(nstart & below) - 1;
            umerge(uf, a, b);
        }
    }
    __syncwarp();

    // ---- Flatten: 2 pointer-jumping passes (preserve low bits) ----
    #pragma unroll
    for (int pass = 0; pass < 2; pass++) {
        for (int i = lane; i < total; i += 32) {
            unsigned w  = uf[i];
            unsigned pw = uf[w >> 16];
            uf[i] = (pw & 0xffff0000u) | (w & 0xffffu);
        }
        __syncwarp();
    }

    // ---- Count: balanced loop; non-roots add static size into root's low bits ----
    for (int i = lane; i < total; i += 32) {
        unsigned w = uf[i];
        int r = (int)(w >> 16);
        if (r != i) {
            r = ufind_ro(uf, r);                 // read-only (adds race on low bits)
            atomicAdd(&uf[r], w & 0xffffu);      // fire-and-forget RED.SHARED
        }
    }
    __syncwarp();

    // ---- Max component; background count (label 0 in reference) competes ----
    int v = 0;
    for (int i = lane; i < total; i += 32) v = max(v, (int)(uf[i] & 0xffffu));
    int bg = 32 - __popc(m);
    #pragma unroll
    for (int o = 16; o > 0; o >>= 1) {
        v  = max(v, __shfl_xor_sync(0xFFFFFFFFu, v, o));
        bg += __shfl_xor_sync(0xFFFFFFFFu, bg, o);
    }

    // ---- Fused reduction: 64th arriver per group finishes the output ----
    if (lane == 0) {
        const int my = max(v, bg);
        const int o = img >> 6;                  // img / PATCHES
        atomicAdd(&g_sum[o], my);
        __threadfence();
        int n = atomicAdd(&g_cnt[o], 1);
        if (n == PATCHES - 1) {
            __threadfence();
            int total_s = atomicExch(&g_sum[o], 0);   // read + reset for replay
            out[o] = (float)(total_s / PATCHES);      // truncating int divide
            atomicExch(&g_cnt[o], 0);                 // reset for replay
        }
    }
}

extern "C" void kernel_launch(void* const* d_in, const int* in_sizes, int n_in,
                              void* d_out, int out_size) {
    const float* x = (const float*)d_in[0];
    float* out = (float*)d_out;
    ccl_kernel<<<N_IMGS / WPB, 32 * WPB>>>(x, out);
}

// round 10
// speedup vs baseline: 2.2937x; 1.2061x over previous
#include <cuda_runtime.h>

// x shape [3, 5, 32, 64, 32, 32] -> 30720 images of 32x32
#define N_IMGS   30720
#define N_OUT    480
#define PATCHES  64
#define HW       1024
#define WPB      8          // warps (=images) per block
#define MAXRUNS  512        // <= 16 runs/row * 32 rows

// Cross-block accumulation scratch; self-resetting each replay.
__device__ int g_sum[N_OUT];
__device__ int g_cnt[N_OUT];

// UF word: [31:16] parent id, [15:0] static run size. During the merge phase
// every store (hook or halve) preserves the low 16 bits, so they stay the
// node's static run size. In the count phase, roots' low bits accumulate the
// component total via atomicAdd (<=1024, never carries into the parent field).

// Find with path halving; returns root and the word observed at the root.
__device__ __forceinline__ int ufind(unsigned* L, int a, unsigned& wroot) {
    while (true) {
        unsigned w = L[a];
        int p = (int)(w >> 16);
        if (p == a) { wroot = w; return a; }
        unsigned pw = L[p];
        int gp = (int)(pw >> 16);
        if (gp == p) { wroot = pw; return p; }
        L[a] = ((unsigned)gp << 16) | (w & 0xffffu);   // halve, keep low bits
        a = gp;
    }
}

// Read-only find (count phase: roots' low bits are concurrently red.add'ed,
// but parent fields are stable and adds never carry into them).
__device__ __forceinline__ int ufind_ro(const unsigned* L, int a) {
    int p = (int)(L[a] >> 16);
    while (p != a) { a = p; p = (int)(L[a] >> 16); }
    return a;
}

__device__ __forceinline__ void umerge(unsigned* L, int a, int b) {
    while (true) {
        unsigned wa, wb;
        a = ufind(L, a, wa);
        b = ufind(L, b, wb);
        if (a == b) return;
        int mn, mx; unsigned wmx;
        if (a < b) { mn = a; mx = b; wmx = wb; }
        else       { mn = b; mx = a; wmx = wa; }
        unsigned old = atomicMin(&L[mx], ((unsigned)mn << 16) | (wmx & 0xffffu));
        if ((int)(old >> 16) == mx) return;    // linked root mx -> mn
        a = mn; b = (int)(old >> 16);          // lost race; merge survivors
    }
}

// Isolate lowest maximal run of 1s (low = lowest set bit of rem).
__device__ __forceinline__ unsigned lowest_run(unsigned rem, unsigned low) {
    return rem & (rem ^ (rem + low));
}

// Spread 8 bits so bit k lands at position 4k.
__device__ __forceinline__ unsigned spread4(unsigned x) {
    x = (x | (x << 12)) & 0x000F000Fu;
    x = (x | (x << 6))  & 0x03030303u;
    x = (x | (x << 3))  & 0x11111111u;
    return x;
}

// One warp per 32x32 image; lane = row.
__global__ void __launch_bounds__(32 * WPB)
ccl_kernel(const float* __restrict__ x, float* __restrict__ out) {
    __shared__ unsigned UF[WPB][MAXRUNS];

    const int lane = threadIdx.x & 31;
    const int warp = threadIdx.x >> 5;
    const int img  = blockIdx.x * WPB + warp;

    // ---- Row bitmasks: 8 coalesced float4 loads, 4 ballots each ----
    const float4* p4 = (const float4*)(x + (size_t)img * HW);
    unsigned c0 = 0, c1 = 0, c2 = 0, c3 = 0;
    #pragma unroll
    for (int i = 0; i < 8; i++) {
        float4 v = __ldcs(&p4[i * 32 + lane]);
        unsigned b0 = __ballot_sync(0xFFFFFFFFu, v.x != 0.0f);
        unsigned b1 = __ballot_sync(0xFFFFFFFFu, v.y != 0.0f);
        unsigned b2 = __ballot_sync(0xFFFFFFFFu, v.z != 0.0f);
        unsigned b3 = __ballot_sync(0xFFFFFFFFu, v.w != 0.0f);
        if ((lane >> 2) == i) {
            int sh = (lane & 3) * 8;
            c0 = (b0 >> sh) & 0xffu;
            c1 = (b1 >> sh) & 0xffu;
            c2 = (b2 >> sh) & 0xffu;
            c3 = (b3 >> sh) & 0xffu;
        }
    }
    const unsigned m = spread4(c0) | (spread4(c1) << 1)
                     | (spread4(c2) << 2) | (spread4(c3) << 3);

    // ---- Run starts; per-row run-id base via warp scan ----
    const unsigned start = m & ~(m << 1);
    const int nmine = __popc(start);
    int scan = nmine;
    #pragma unroll
    for (int o = 1; o < 32; o <<= 1) {
        int v = __shfl_up_sync(0xFFFFFFFFu, scan, o);
        if (lane >= o) scan += v;
    }
    const int base  = scan - nmine;
    const int total = __shfl_sync(0xFFFFFFFFu, scan, 31);

    // ---- Init: each lane writes its runs' (parent=self | size) words ----
    unsigned* uf = UF[warp];
    {
        unsigned rem = m;
        int idx = base;
        while (rem) {
            unsigned low   = rem & (unsigned)(-(int)rem);
            unsigned rmask = lowest_run(rem, low);
            rem &= ~rmask;
            uf[idx] = ((unsigned)idx << 16) | (unsigned)__popc(rmask);
            idx++;
        }
    }
    __syncwarp();

    // ---- Merge inter-row edges: one edge per maximal segment of m & nextrow ----
    unsigned nm     = __shfl_down_sync(0xFFFFFFFFu, m, 1);
    unsigned nstart = __shfl_down_sync(0xFFFFFFFFu, start, 1);
    int      nbase  = __shfl_down_sync(0xFFFFFFFFu, base, 1);
    if (lane == 31) nm = 0;
    {
        unsigned ov   = m & nm;
        unsigned segs = ov & ~(ov << 1);
        while (segs) {
            int j = __ffs(segs) - 1;
            segs &= segs - 1;
            unsigned below = (2u << j) - 1;            // bits 0..j (j=31 -> all)
            int a = base  + __popc(start  & below) - 1;
            int b = nbase + __popc(nstart & below) - 1;
            umerge(uf, a, b);
        }
    }
    __syncwarp();

    // ---- Fused count + max: non-roots add their static size into the root;
    //      the LAST adder to a root observes the component's final total.
    //      Partial sums from earlier adders only underestimate (safe for max).
    int v = 0;
    for (int i = lane; i < total; i += 32) {
        unsigned w  = uf[i];
        int r       = (int)(w >> 16);
        unsigned sz = w & 0xffffu;
        if (r == i) {
            v = max(v, (int)sz);                       // covers singleton roots
        } else {
            r = ufind_ro(uf, r);
            unsigned old = atomicAdd(&uf[r], sz);
            v = max(v, (int)((old + sz) & 0xffffu));   // last adder sees total
        }
    }

    // ---- Background count (label 0 in reference) competes for the max ----
    int bg = 32 - __popc(m);
    #pragma unroll
    for (int o = 16; o > 0; o >>= 1) {
        v  = max(v, __shfl_xor_sync(0xFFFFFFFFu, v, o));
        bg += __shfl_xor_sync(0xFFFFFFFFu, bg, o);
    }

    // ---- Fused reduction: 64th arriver per group finishes the output ----
    if (lane == 0) {
        const int my = max(v, bg);
        const int o = img >> 6;                        // img / PATCHES
        atomicAdd(&g_sum[o], my);
        __threadfence();
        int n = atomicAdd(&g_cnt[o], 1);
        if (n == PATCHES - 1) {
            __threadfence();
            int total_s = atomicExch(&g_sum[o], 0);    // read + reset for replay
            out[o] = (float)(total_s / PATCHES);       // truncating int divide
            atomicExch(&g_cnt[o], 0);                  // reset for replay
        }
    }
}

extern "C" void kernel_launch(void* const* d_in, const int* in_sizes, int n_in,
                              void* d_out, int out_size) {
    const float* x = (const float*)d_in[0];
    float* out = (float*)d_out;
    ccl_kernel<<<N_IMGS / WPB, 32 * WPB>>>(x, out);
}